// round 9
// baseline (speedup 1.0000x reference)
#include <cuda_runtime.h>
#include <math.h>

#define BATCH     32768
#define IN_DIM    64
#define NUM_BINS  10
#define EMBED_DIM 64
#define NTHRESH   9

#define GRID   444                // 148 SMs * 3 blocks co-resident (<=83 regs)
#define TPB    256
#define MMB    (GRID - 1)         // blocks 0..442 min/max; block 443 bins+M
#define T1     (MMB * TPB)        // %16==0 -> float4 column-group invariant
#define NV     (BATCH * 16)
#define NWARP  (GRID * 8)         // 3552 phase-2 warps
#define SLOTS  16                 // atomic contention depth 443 -> ~28

#define E8(x)   x,x,x,x,x,x,x,x
#define E64(x)  E8(x),E8(x),E8(x),E8(x),E8(x),E8(x),E8(x),E8(x)
#define E256(x) E64(x),E64(x),E64(x),E64(x)
#define E1K(x)  E256(x),E256(x),E256(x),E256(x)

// monotone float<->uint encoding: unsigned order == float order (NaN-free data)
__device__ __forceinline__ unsigned fenc(float f) {
    unsigned u = __float_as_uint(f);
    return (u & 0x80000000u) ? ~u : (u | 0x80000000u);
}
__device__ __forceinline__ float fdec(unsigned e) {
    unsigned u = (e & 0x80000000u) ? (e ^ 0x80000000u) : ~e;
    return __uint_as_float(u);
}

// ---- scratch (device globals; no allocation allowed) ----
__device__ unsigned g_minenc[SLOTS * IN_DIM] = { E1K(0xFF800000u) };  // enc(+INF)
__device__ unsigned g_maxenc[SLOTS * IN_DIM] = { E1K(0x007FFFFFu) };  // enc(-INF)
__device__ float    g_bins[NTHRESH];
__device__ float    g_thr[IN_DIM * NTHRESH];   // thr[c][k]: pred <=> x > thr
__device__ float    g_M[NUM_BINS * EMBED_DIM];
__device__ int      g_count;
__device__ unsigned g_release;

// exact boundary: largest float X with fdiv_rn(fsub_rn(X,mn),dn) <= bk
__device__ float find_thr(float mn, float dn, float bk) {
    const unsigned ELO = 0x007FFFFFu;   // enc(-inf): predicate false
    const unsigned EHI = 0xFF800000u;   // enc(+inf): predicate true
    double gd = (double)mn + (double)bk * (double)dn;
    float gf = (float)gd;
    if (!isfinite(gf)) gf = (gd > 0.0) ? 3.0e38f : -3.0e38f;
    unsigned ge = fenc(gf);
    if (ge < ELO) ge = ELO;
    if (ge > EHI) ge = EHI;

    unsigned lo, hi;
    if (__fdiv_rn(fdec(ge) - mn, dn) > bk) {
        hi = ge; lo = ELO;
        unsigned step = 1;
        unsigned p = ge;
        while (p > ELO) {
            p = (p - ELO > step) ? p - step : ELO;
            if (!(__fdiv_rn(fdec(p) - mn, dn) > bk)) { lo = p; break; }
            hi = p;
            step <<= 1;
        }
    } else {
        lo = ge; hi = EHI;
        unsigned step = 1;
        unsigned p = ge;
        while (p < EHI) {
            p = (EHI - p > step) ? p + step : EHI;
            if (__fdiv_rn(fdec(p) - mn, dn) > bk) { hi = p; break; }
            lo = p;
            step <<= 1;
        }
    }
    while (hi - lo > 1) {
        unsigned mid = lo + ((hi - lo) >> 1);
        if (__fdiv_rn(fdec(mid) - mn, dn) > bk) hi = mid; else lo = mid;
    }
    return fdec(lo);
}

__global__ void __launch_bounds__(TPB, 3)
dybem_fused(const float*  __restrict__ x,
            const float*  __restrict__ logits,
            const float*  __restrict__ embed,
            const float*  __restrict__ W,
            const float*  __restrict__ bias,
            float*        __restrict__ out) {
    const int tid  = threadIdx.x;
    const int lane = tid & 31;
    const int wrp  = tid >> 5;
    const int b    = blockIdx.x;

    __shared__ unsigned s_snap;
    __shared__ int      s_ticket;
    __shared__ float smm[2][8][16][4];
    __shared__ float sWt[EMBED_DIM * 65];
    __shared__ float sEm[NUM_BINS * EMBED_DIM];
    __shared__ float sE[NUM_BINS];
    __shared__ float sMn[IN_DIM], sDn[IN_DIM];

    if (tid == 0) s_snap = *(volatile unsigned*)&g_release;
    __syncthreads();

    // ================= PHASE 1 =================
    if (b < MMB) {
        const float4* __restrict__ x4 = (const float4*)x;
        const int tg = b * TPB + tid;
        float mn0 =  INFINITY, mn1 =  INFINITY, mn2 =  INFINITY, mn3 =  INFINITY;
        float mx0 = -INFINITY, mx1 = -INFINITY, mx2 = -INFINITY, mx3 = -INFINITY;
        #pragma unroll 5
        for (int idx = tg; idx < NV; idx += T1) {
            float4 v = x4[idx];
            mn0 = fminf(mn0, v.x); mx0 = fmaxf(mx0, v.x);
            mn1 = fminf(mn1, v.y); mx1 = fmaxf(mx1, v.y);
            mn2 = fminf(mn2, v.z); mx2 = fmaxf(mx2, v.z);
            mn3 = fminf(mn3, v.w); mx3 = fmaxf(mx3, v.w);
        }
        mn0 = fminf(mn0, __shfl_down_sync(0xffffffffu, mn0, 16));
        mn1 = fminf(mn1, __shfl_down_sync(0xffffffffu, mn1, 16));
        mn2 = fminf(mn2, __shfl_down_sync(0xffffffffu, mn2, 16));
        mn3 = fminf(mn3, __shfl_down_sync(0xffffffffu, mn3, 16));
        mx0 = fmaxf(mx0, __shfl_down_sync(0xffffffffu, mx0, 16));
        mx1 = fmaxf(mx1, __shfl_down_sync(0xffffffffu, mx1, 16));
        mx2 = fmaxf(mx2, __shfl_down_sync(0xffffffffu, mx2, 16));
        mx3 = fmaxf(mx3, __shfl_down_sync(0xffffffffu, mx3, 16));
        if (lane < 16) {
            smm[0][wrp][lane][0] = mn0; smm[0][wrp][lane][1] = mn1;
            smm[0][wrp][lane][2] = mn2; smm[0][wrp][lane][3] = mn3;
            smm[1][wrp][lane][0] = mx0; smm[1][wrp][lane][1] = mx1;
            smm[1][wrp][lane][2] = mx2; smm[1][wrp][lane][3] = mx3;
        }
        __syncthreads();
        if (tid < IN_DIM) {
            const int g = tid >> 2, q = tid & 3;
            float a =  INFINITY, c = -INFINITY;
            #pragma unroll
            for (int w = 0; w < 8; w++) {
                a = fminf(a, smm[0][w][g][q]);
                c = fmaxf(c, smm[1][w][g][q]);
            }
            const int slot = (b & (SLOTS - 1)) * IN_DIM + tid;
            atomicMin(&g_minenc[slot], fenc(a));
            atomicMax(&g_maxenc[slot], fenc(c));
        }
    } else {
        // --- block MMB: bins (warp 0, parallel exp) + M = embed @ W^T ---
        if (wrp == 0) {
            float li = (lane < NUM_BINS) ? logits[lane] : -INFINITY;
            float m = li;
            #pragma unroll
            for (int d = 16; d >= 1; d >>= 1)
                m = fmaxf(m, __shfl_xor_sync(0xffffffffu, m, d));
            if (lane < NUM_BINS)
                sE[lane] = (float)exp((double)(li - m));
            __syncwarp();
            if (lane == 0) {
                float s = 0.f;
                #pragma unroll
                for (int i = 0; i < NUM_BINS; i++) s += sE[i];
                float cum = 0.f;
                #pragma unroll
                for (int i = 0; i < NUM_BINS; i++) {
                    cum += __fdiv_rn(sE[i], s);
                    if (i < NTHRESH) g_bins[i] = cum;
                }
            }
        }
        #pragma unroll
        for (int i = tid; i < EMBED_DIM * EMBED_DIM; i += TPB) {
            const int f = i >> 6, e = i & 63;
            sWt[e * 65 + f] = W[i];
        }
        for (int i = tid; i < NUM_BINS * EMBED_DIM; i += TPB)
            sEm[i] = embed[i];
        __syncthreads();
        for (int i = tid; i < NUM_BINS * EMBED_DIM; i += TPB) {
            const int k = i >> 6, f = i & 63;
            const float* em = sEm + k * EMBED_DIM;
            float s = 0.f;
            #pragma unroll 16
            for (int e2 = 0; e2 < EMBED_DIM; e2++)
                s = fmaf(em[e2], sWt[e2 * 65 + f], s);
            g_M[i] = s;
        }
    }

    // ================= GRID BARRIER =================
    __threadfence();
    __syncthreads();
    if (tid == 0) s_ticket = atomicAdd(&g_count, 1);
    __syncthreads();

    if (s_ticket == GRID - 1) {
        __threadfence();  // acquire all atomics + g_bins + g_M
        if (tid < IN_DIM) {
            unsigned emin = 0xFF800000u, emax = 0x007FFFFFu;
            #pragma unroll
            for (int s = 0; s < SLOTS; s++) {
                unsigned a = *(volatile unsigned*)&g_minenc[s * IN_DIM + tid];
                unsigned c = *(volatile unsigned*)&g_maxenc[s * IN_DIM + tid];
                emin = (a < emin) ? a : emin;
                emax = (c > emax) ? c : emax;
                g_minenc[s * IN_DIM + tid] = 0xFF800000u;   // reset for replay
                g_maxenc[s * IN_DIM + tid] = 0x007FFFFFu;
            }
            float a = fdec(emin), c = fdec(emax);
            sMn[tid] = a;
            sDn[tid] = (c - a) + 1e-6f;
        }
        __syncthreads();
        for (int i = tid; i < IN_DIM * NTHRESH; i += TPB) {
            const int c = i / NTHRESH, k = i % NTHRESH;
            g_thr[i] = find_thr(sMn[c], sDn[c], g_bins[k]);
        }
        if (tid == 0) g_count = 0;
        __threadfence();
        __syncthreads();
        if (tid == 0) atomicAdd(&g_release, 1u);
    }

    if (tid == 0) {
        while (*(volatile unsigned*)&g_release == s_snap) { __nanosleep(32); }
    }
    __syncthreads();
    __threadfence();

    // ================= PHASE 2 =================
    const int c0 = lane * 2;
    const int c1 = c0 + 1;
    const int w  = b * 8 + wrp;

    float t0[NTHRESH], t1[NTHRESH];
    #pragma unroll
    for (int k = 0; k < NTHRESH; k++) {
        t0[k] = g_thr[c0 * NTHRESH + k];
        t1[k] = g_thr[c1 * NTHRESH + k];
    }

    const float base0 = 64.f * (g_M[c0] + bias[c0]);
    const float base1 = 64.f * (g_M[c1] + bias[c1]);

    float D0[NTHRESH], D1[NTHRESH];
    #pragma unroll
    for (int k = 0; k < NTHRESH; k++) {
        D0[k] = g_M[(k + 1) * EMBED_DIM + c0] - g_M[k * EMBED_DIM + c0];
        D1[k] = g_M[(k + 1) * EMBED_DIM + c1] - g_M[k * EMBED_DIM + c1];
    }

    const float2* __restrict__ x2   = (const float2*)x;
    float2* __restrict__       out2 = (float2*)out;

    const unsigned KM = 0x4B400000u;     // float 12582912.0f
    const float    KC = 12582912.0f;     // (pf - KC) is exact for counts<=255

    int r           = (int)(((long long)w       * BATCH) / NWARP);
    const int r_end = (int)(((long long)(w + 1) * BATCH) / NWARP);

    for (; r + 4 <= r_end; r += 4) {
        const float2* xp = x2 + r * 32 + lane;
        float2 v0 = xp[0];
        float2 v1 = xp[32];
        float2 v2 = xp[64];
        float2 v3 = xp[96];

        unsigned qa0 = 0, qa1 = 0;
        unsigned qb0 = 0, qb1 = 0;
        unsigned qc0 = 0, qc1 = 0;
        unsigned qd0 = 0, qd1 = 0;
        unsigned q2  = 0;                 // k=8 counts, one byte per row
        #pragma unroll
        for (int k = 0; k < 4; k++) {
            const unsigned wgt = 1u << (8 * k);
            qa0 += (v0.x > t0[k]) ? wgt : 0u;  qa0 += (v0.y > t1[k]) ? wgt : 0u;
            qb0 += (v1.x > t0[k]) ? wgt : 0u;  qb0 += (v1.y > t1[k]) ? wgt : 0u;
            qc0 += (v2.x > t0[k]) ? wgt : 0u;  qc0 += (v2.y > t1[k]) ? wgt : 0u;
            qd0 += (v3.x > t0[k]) ? wgt : 0u;  qd0 += (v3.y > t1[k]) ? wgt : 0u;
        }
        #pragma unroll
        for (int k = 4; k < 8; k++) {
            const unsigned wgt = 1u << (8 * (k - 4));
            qa1 += (v0.x > t0[k]) ? wgt : 0u;  qa1 += (v0.y > t1[k]) ? wgt : 0u;
            qb1 += (v1.x > t0[k]) ? wgt : 0u;  qb1 += (v1.y > t1[k]) ? wgt : 0u;
            qc1 += (v2.x > t0[k]) ? wgt : 0u;  qc1 += (v2.y > t1[k]) ? wgt : 0u;
            qd1 += (v3.x > t0[k]) ? wgt : 0u;  qd1 += (v3.y > t1[k]) ? wgt : 0u;
        }
        q2 += (v0.x > t0[8]) ? 0x00000001u : 0u;  q2 += (v0.y > t1[8]) ? 0x00000001u : 0u;
        q2 += (v1.x > t0[8]) ? 0x00000100u : 0u;  q2 += (v1.y > t1[8]) ? 0x00000100u : 0u;
        q2 += (v2.x > t0[8]) ? 0x00010000u : 0u;  q2 += (v2.y > t1[8]) ? 0x00010000u : 0u;
        q2 += (v3.x > t0[8]) ? 0x01000000u : 0u;  q2 += (v3.y > t1[8]) ? 0x01000000u : 0u;

        // 9 byte-wise warp sums (counts <= 64 per byte, no carry)
        qa0 = __reduce_add_sync(0xffffffffu, qa0);
        qa1 = __reduce_add_sync(0xffffffffu, qa1);
        qb0 = __reduce_add_sync(0xffffffffu, qb0);
        qb1 = __reduce_add_sync(0xffffffffu, qb1);
        qc0 = __reduce_add_sync(0xffffffffu, qc0);
        qc1 = __reduce_add_sync(0xffffffffu, qc1);
        qd0 = __reduce_add_sync(0xffffffffu, qd0);
        qd1 = __reduce_add_sync(0xffffffffu, qd1);
        q2  = __reduce_add_sync(0xffffffffu, q2);

        float a0 = base0, a1 = base1, b0 = base0, b1 = base1;
        float cc0 = base0, cc1 = base1, d0 = base0, d1 = base1;
        #pragma unroll
        for (int k = 0; k < 9; k++) {
            // byte -> float via PRMT splice into 0x4B400000 then exact subtract
            unsigned ua = (k < 4) ? __byte_perm(qa0, KM, 0x7640 + k)
                        : (k < 8) ? __byte_perm(qa1, KM, 0x7640 + (k - 4))
                                  : __byte_perm(q2,  KM, 0x7640);
            unsigned ub = (k < 4) ? __byte_perm(qb0, KM, 0x7640 + k)
                        : (k < 8) ? __byte_perm(qb1, KM, 0x7640 + (k - 4))
                                  : __byte_perm(q2,  KM, 0x7641);
            unsigned uc = (k < 4) ? __byte_perm(qc0, KM, 0x7640 + k)
                        : (k < 8) ? __byte_perm(qc1, KM, 0x7640 + (k - 4))
                                  : __byte_perm(q2,  KM, 0x7642);
            unsigned ud = (k < 4) ? __byte_perm(qd0, KM, 0x7640 + k)
                        : (k < 8) ? __byte_perm(qd1, KM, 0x7640 + (k - 4))
                                  : __byte_perm(q2,  KM, 0x7643);
            float fa = __uint_as_float(ua) - KC;
            float fb = __uint_as_float(ub) - KC;
            float fc = __uint_as_float(uc) - KC;
            float fd = __uint_as_float(ud) - KC;
            a0  = fmaf(fa, D0[k], a0);   a1  = fmaf(fa, D1[k], a1);
            b0  = fmaf(fb, D0[k], b0);   b1  = fmaf(fb, D1[k], b1);
            cc0 = fmaf(fc, D0[k], cc0);  cc1 = fmaf(fc, D1[k], cc1);
            d0  = fmaf(fd, D0[k], d0);   d1  = fmaf(fd, D1[k], d1);
        }
        float2* op = out2 + r * 32 + lane;
        op[0]  = make_float2(a0, a1);
        op[32] = make_float2(b0, b1);
        op[64] = make_float2(cc0, cc1);
        op[96] = make_float2(d0, d1);
    }

    for (; r < r_end; r++) {
        float2 v0 = x2[r * 32 + lane];
        unsigned qa0 = 0, qa1 = 0, q2 = 0;
        #pragma unroll
        for (int k = 0; k < 4; k++) {
            const unsigned wgt = 1u << (8 * k);
            qa0 += (v0.x > t0[k]) ? wgt : 0u;  qa0 += (v0.y > t1[k]) ? wgt : 0u;
        }
        #pragma unroll
        for (int k = 4; k < 8; k++) {
            const unsigned wgt = 1u << (8 * (k - 4));
            qa1 += (v0.x > t0[k]) ? wgt : 0u;  qa1 += (v0.y > t1[k]) ? wgt : 0u;
        }
        q2 += (v0.x > t0[8]) ? 1u : 0u;  q2 += (v0.y > t1[8]) ? 1u : 0u;

        qa0 = __reduce_add_sync(0xffffffffu, qa0);
        qa1 = __reduce_add_sync(0xffffffffu, qa1);
        q2  = __reduce_add_sync(0xffffffffu, q2);

        float a0 = base0, a1 = base1;
        #pragma unroll
        for (int k = 0; k < 9; k++) {
            unsigned ua = (k < 4) ? __byte_perm(qa0, KM, 0x7640 + k)
                        : (k < 8) ? __byte_perm(qa1, KM, 0x7640 + (k - 4))
                                  : __byte_perm(q2,  KM, 0x7640);
            float fa = __uint_as_float(ua) - KC;
            a0 = fmaf(fa, D0[k], a0);
            a1 = fmaf(fa, D1[k], a1);
        }
        out2[r * 32 + lane] = make_float2(a0, a1);
    }
}

extern "C" void kernel_launch(void* const* d_in, const int* in_sizes, int n_in,
                              void* d_out, int out_size) {
    const float* x      = (const float*)d_in[0];
    const float* logits = (const float*)d_in[1];
    const float* embed  = (const float*)d_in[2];
    const float* W      = (const float*)d_in[3];
    const float* bias   = (const float*)d_in[4];
    float* out          = (float*)d_out;

    dybem_fused<<<GRID, TPB>>>(x, logits, embed, W, bias, out);
}

// round 10
// speedup vs baseline: 1.2610x; 1.2610x over previous
#include <cuda_runtime.h>
#include <math.h>

#define BATCH     32768
#define IN_DIM    64
#define NUM_BINS  10
#define EMBED_DIM 64
#define NTHRESH   9

#define TPB        256
#define K1_MBLK    1024                 // minmax blocks (block 1024 = bins+M)
#define T1         (K1_MBLK * TPB)      // 262144 -> 2 float4 per thread
#define NV         (BATCH * 16)         // 524288 float4s
#define SLOTS      32
#define K3_BLOCKS  1024                 // 8192 warps * 4 rows = 32768

#define E8(x)   x,x,x,x,x,x,x,x
#define E64(x)  E8(x),E8(x),E8(x),E8(x),E8(x),E8(x),E8(x),E8(x)
#define E256(x) E64(x),E64(x),E64(x),E64(x)
#define E1K(x)  E256(x),E256(x),E256(x),E256(x)
#define E2K(x)  E1K(x),E1K(x)

// monotone float<->uint encoding (NaN-free data)
__device__ __forceinline__ unsigned fenc(float f) {
    unsigned u = __float_as_uint(f);
    return (u & 0x80000000u) ? ~u : (u | 0x80000000u);
}
__device__ __forceinline__ float fdec(unsigned e) {
    unsigned u = (e & 0x80000000u) ? (e ^ 0x80000000u) : ~e;
    return __uint_as_float(u);
}

// ---- scratch (device globals; no allocation allowed) ----
__device__ unsigned g_minenc[SLOTS * IN_DIM] = { E2K(0xFF800000u) };  // enc(+INF)
__device__ unsigned g_maxenc[SLOTS * IN_DIM] = { E2K(0x007FFFFFu) };  // enc(-INF)
__device__ float    g_bins[NTHRESH];
__device__ float    g_M[NUM_BINS * EMBED_DIM];
__device__ float4   g_nd4[32];          // per lane: {mn[2l], dn[2l], mn[2l+1], dn[2l+1]}
__device__ float2   g_D2[NTHRESH * 32]; // D[k][c] pairs: g_D2[k*32+l] = {D[k][2l], D[k][2l+1]}
__device__ float2   g_base2[32];        // base[c] pairs

// ================= K1: min/max partials + (block K1_MBLK) bins + M =========
__global__ void __launch_bounds__(TPB)
k1_stats(const float4* __restrict__ x4,
         const float*  __restrict__ logits,
         const float*  __restrict__ embed,
         const float*  __restrict__ W) {
    const int tid  = threadIdx.x;
    const int lane = tid & 31;
    const int wrp  = tid >> 5;
    const int b    = blockIdx.x;

    __shared__ float smm[2][8][16][4];
    __shared__ float sWt[EMBED_DIM * 65];
    __shared__ float sEm[NUM_BINS * EMBED_DIM];
    __shared__ float sE[NUM_BINS];

    if (b < K1_MBLK) {
        // --- min/max: 2 independent float4 loads per thread (col-group = tid%16) ---
        const int tg = b * TPB + tid;
        float4 va = x4[tg];
        float4 vb = x4[tg + T1];
        float mn0 = fminf(va.x, vb.x), mx0 = fmaxf(va.x, vb.x);
        float mn1 = fminf(va.y, vb.y), mx1 = fmaxf(va.y, vb.y);
        float mn2 = fminf(va.z, vb.z), mx2 = fmaxf(va.z, vb.z);
        float mn3 = fminf(va.w, vb.w), mx3 = fmaxf(va.w, vb.w);

        mn0 = fminf(mn0, __shfl_down_sync(0xffffffffu, mn0, 16));
        mn1 = fminf(mn1, __shfl_down_sync(0xffffffffu, mn1, 16));
        mn2 = fminf(mn2, __shfl_down_sync(0xffffffffu, mn2, 16));
        mn3 = fminf(mn3, __shfl_down_sync(0xffffffffu, mn3, 16));
        mx0 = fmaxf(mx0, __shfl_down_sync(0xffffffffu, mx0, 16));
        mx1 = fmaxf(mx1, __shfl_down_sync(0xffffffffu, mx1, 16));
        mx2 = fmaxf(mx2, __shfl_down_sync(0xffffffffu, mx2, 16));
        mx3 = fmaxf(mx3, __shfl_down_sync(0xffffffffu, mx3, 16));
        if (lane < 16) {
            smm[0][wrp][lane][0] = mn0; smm[0][wrp][lane][1] = mn1;
            smm[0][wrp][lane][2] = mn2; smm[0][wrp][lane][3] = mn3;
            smm[1][wrp][lane][0] = mx0; smm[1][wrp][lane][1] = mx1;
            smm[1][wrp][lane][2] = mx2; smm[1][wrp][lane][3] = mx3;
        }
        __syncthreads();
        if (tid < IN_DIM) {
            const int g = tid >> 2, q = tid & 3;
            float a =  INFINITY, c = -INFINITY;
            #pragma unroll
            for (int w = 0; w < 8; w++) {
                a = fminf(a, smm[0][w][g][q]);
                c = fmaxf(c, smm[1][w][g][q]);
            }
            const int slot = (b & (SLOTS - 1)) * IN_DIM + tid;
            atomicMin(&g_minenc[slot], fenc(a));
            atomicMax(&g_maxenc[slot], fenc(c));
        }
    } else {
        // --- bins (warp 0, parallel exp) + M = embed @ W^T via smem staging ---
        if (wrp == 0) {
            float li = (lane < NUM_BINS) ? logits[lane] : -INFINITY;
            float m = li;
            #pragma unroll
            for (int d = 16; d >= 1; d >>= 1)
                m = fmaxf(m, __shfl_xor_sync(0xffffffffu, m, d));
            if (lane < NUM_BINS)
                sE[lane] = (float)exp((double)(li - m));   // correctly-rounded f32
            __syncwarp();
            if (lane == 0) {
                float s = 0.f;
                #pragma unroll
                for (int i = 0; i < NUM_BINS; i++) s += sE[i];   // fixed order
                float cum = 0.f;
                #pragma unroll
                for (int i = 0; i < NUM_BINS; i++) {
                    cum += __fdiv_rn(sE[i], s);                   // IEEE div
                    if (i < NTHRESH) g_bins[i] = cum;
                }
            }
        }
        #pragma unroll
        for (int i = tid; i < EMBED_DIM * EMBED_DIM; i += TPB) {
            const int f = i >> 6, e = i & 63;
            sWt[e * 65 + f] = W[i];           // coalesced read, conflict-free write
        }
        for (int i = tid; i < NUM_BINS * EMBED_DIM; i += TPB)
            sEm[i] = embed[i];
        __syncthreads();
        for (int i = tid; i < NUM_BINS * EMBED_DIM; i += TPB) {
            const int k = i >> 6, f = i & 63;
            const float* em = sEm + k * EMBED_DIM;
            float s = 0.f;
            #pragma unroll 16
            for (int e2 = 0; e2 < EMBED_DIM; e2++)
                s = fmaf(em[e2], sWt[e2 * 65 + f], s);
            g_M[i] = s;
        }
    }
}

// ================= K2: finalize mn/dn (+slot reset) + D/base precompute ====
__global__ void __launch_bounds__(1024)
k2_finalize(const float* __restrict__ bias) {
    const int tid = threadIdx.x;

    if (tid < 512) {
        // 8 threads per column, 4 slots each; shfl reduce within the 8
        const int col = tid >> 3;    // 0..63 (8 consecutive lanes share a col)
        const int sub = tid & 7;
        unsigned emin = 0xFF800000u, emax = 0x007FFFFFu;
        #pragma unroll
        for (int s = sub; s < SLOTS; s += 8) {
            unsigned a = g_minenc[s * IN_DIM + col];
            unsigned c = g_maxenc[s * IN_DIM + col];
            emin = (a < emin) ? a : emin;
            emax = (c > emax) ? c : emax;
            g_minenc[s * IN_DIM + col] = 0xFF800000u;   // reset for next replay
            g_maxenc[s * IN_DIM + col] = 0x007FFFFFu;
        }
        #pragma unroll
        for (int d = 4; d >= 1; d >>= 1) {
            unsigned a = __shfl_xor_sync(0xffffffffu, emin, d);
            unsigned c = __shfl_xor_sync(0xffffffffu, emax, d);
            emin = (a < emin) ? a : emin;
            emax = (c > emax) ? c : emax;
        }
        if (sub == 0) {
            float a = fdec(emin), c = fdec(emax);
            float dn = (c - a) + 1e-6f;
            float* nd = (float*)g_nd4;
            nd[(col >> 1) * 4 + (col & 1) * 2]     = a;   // mn
            nd[(col >> 1) * 4 + (col & 1) * 2 + 1] = dn;  // dn
        }
    } else {
        // D[k][c] = M[k+1][c] - M[k][c] (576 values) and base (64 values)
        const int i = tid - 512;           // 0..511
        float* gD = (float*)g_D2;
        gD[i] = g_M[i + 64] - g_M[i];
        if (i < 64)
            gD[512 + i] = g_M[512 + i + 64] - g_M[512 + i];
        if (i >= 64 && i < 128) {
            const int c = i - 64;
            ((float*)g_base2)[c] = 64.f * (g_M[c] + bias[c]);
        }
    }
}

// ================= K3: main — exactly 4 rows per warp, no loops =============
// out[b,f] = base[f] + sum_{k=1..9} c_k * D[k][f];  c_k via packed-byte REDUX.
__global__ void __launch_bounds__(TPB)
k3_main(const float* __restrict__ x, float* __restrict__ out) {
    const int lane = threadIdx.x & 31;
    const int wrp  = threadIdx.x >> 5;
    const int w    = blockIdx.x * 8 + wrp;     // 0..8191
    const int r    = w * 4;

    const float4 nd = g_nd4[lane];
    const float mn0 = nd.x, dn0 = nd.y, mn1 = nd.z, dn1 = nd.w;

    float bins[NTHRESH];
    #pragma unroll
    for (int k = 0; k < NTHRESH; k++) bins[k] = g_bins[k];

    float2 Dv[NTHRESH];
    #pragma unroll
    for (int k = 0; k < NTHRESH; k++) Dv[k] = g_D2[k * 32 + lane];

    const float2 bs = g_base2[lane];

    const float2* __restrict__ xp = (const float2*)x + (size_t)r * 32 + lane;
    float2 v0 = xp[0];
    float2 v1 = xp[32];
    float2 v2 = xp[64];
    float2 v3 = xp[96];

    // exact reference f32 sequence: sub then IEEE divide
    float xa0 = __fdiv_rn(v0.x - mn0, dn0), xa1 = __fdiv_rn(v0.y - mn1, dn1);
    float xb0 = __fdiv_rn(v1.x - mn0, dn0), xb1 = __fdiv_rn(v1.y - mn1, dn1);
    float xc0 = __fdiv_rn(v2.x - mn0, dn0), xc1 = __fdiv_rn(v2.y - mn1, dn1);
    float xd0 = __fdiv_rn(v3.x - mn0, dn0), xd1 = __fdiv_rn(v3.y - mn1, dn1);

    unsigned qa0 = 0, qa1 = 0;
    unsigned qb0 = 0, qb1 = 0;
    unsigned qc0 = 0, qc1 = 0;
    unsigned qd0 = 0, qd1 = 0;
    unsigned q2  = 0;                   // k=8 counts, one byte per row
    #pragma unroll
    for (int k = 0; k < 4; k++) {
        const unsigned wgt = 1u << (8 * k);
        qa0 += (xa0 > bins[k]) ? wgt : 0u;  qa0 += (xa1 > bins[k]) ? wgt : 0u;
        qb0 += (xb0 > bins[k]) ? wgt : 0u;  qb0 += (xb1 > bins[k]) ? wgt : 0u;
        qc0 += (xc0 > bins[k]) ? wgt : 0u;  qc0 += (xc1 > bins[k]) ? wgt : 0u;
        qd0 += (xd0 > bins[k]) ? wgt : 0u;  qd0 += (xd1 > bins[k]) ? wgt : 0u;
    }
    #pragma unroll
    for (int k = 4; k < 8; k++) {
        const unsigned wgt = 1u << (8 * (k - 4));
        qa1 += (xa0 > bins[k]) ? wgt : 0u;  qa1 += (xa1 > bins[k]) ? wgt : 0u;
        qb1 += (xb0 > bins[k]) ? wgt : 0u;  qb1 += (xb1 > bins[k]) ? wgt : 0u;
        qc1 += (xc0 > bins[k]) ? wgt : 0u;  qc1 += (xc1 > bins[k]) ? wgt : 0u;
        qd1 += (xd0 > bins[k]) ? wgt : 0u;  qd1 += (xd1 > bins[k]) ? wgt : 0u;
    }
    q2 += (xa0 > bins[8]) ? 0x00000001u : 0u;  q2 += (xa1 > bins[8]) ? 0x00000001u : 0u;
    q2 += (xb0 > bins[8]) ? 0x00000100u : 0u;  q2 += (xb1 > bins[8]) ? 0x00000100u : 0u;
    q2 += (xc0 > bins[8]) ? 0x00010000u : 0u;  q2 += (xc1 > bins[8]) ? 0x00010000u : 0u;
    q2 += (xd0 > bins[8]) ? 0x01000000u : 0u;  q2 += (xd1 > bins[8]) ? 0x01000000u : 0u;

    qa0 = __reduce_add_sync(0xffffffffu, qa0);
    qa1 = __reduce_add_sync(0xffffffffu, qa1);
    qb0 = __reduce_add_sync(0xffffffffu, qb0);
    qb1 = __reduce_add_sync(0xffffffffu, qb1);
    qc0 = __reduce_add_sync(0xffffffffu, qc0);
    qc1 = __reduce_add_sync(0xffffffffu, qc1);
    qd0 = __reduce_add_sync(0xffffffffu, qd0);
    qd1 = __reduce_add_sync(0xffffffffu, qd1);
    q2  = __reduce_add_sync(0xffffffffu, q2);

    const unsigned KM = 0x4B400000u;
    const float    KC = 12582912.0f;

    float a0 = bs.x, a1 = bs.y, b0 = bs.x, b1 = bs.y;
    float cc0 = bs.x, cc1 = bs.y, d0 = bs.x, d1 = bs.y;
    #pragma unroll
    for (int k = 0; k < 9; k++) {
        unsigned ua = (k < 4) ? __byte_perm(qa0, KM, 0x7640 + k)
                    : (k < 8) ? __byte_perm(qa1, KM, 0x7640 + (k - 4))
                              : __byte_perm(q2,  KM, 0x7640);
        unsigned ub = (k < 4) ? __byte_perm(qb0, KM, 0x7640 + k)
                    : (k < 8) ? __byte_perm(qb1, KM, 0x7640 + (k - 4))
                              : __byte_perm(q2,  KM, 0x7641);
        unsigned uc = (k < 4) ? __byte_perm(qc0, KM, 0x7640 + k)
                    : (k < 8) ? __byte_perm(qc1, KM, 0x7640 + (k - 4))
                              : __byte_perm(q2,  KM, 0x7642);
        unsigned ud = (k < 4) ? __byte_perm(qd0, KM, 0x7640 + k)
                    : (k < 8) ? __byte_perm(qd1, KM, 0x7640 + (k - 4))
                              : __byte_perm(q2,  KM, 0x7643);
        float fa = __uint_as_float(ua) - KC;
        float fb = __uint_as_float(ub) - KC;
        float fc = __uint_as_float(uc) - KC;
        float fd = __uint_as_float(ud) - KC;
        a0  = fmaf(fa, Dv[k].x, a0);   a1  = fmaf(fa, Dv[k].y, a1);
        b0  = fmaf(fb, Dv[k].x, b0);   b1  = fmaf(fb, Dv[k].y, b1);
        cc0 = fmaf(fc, Dv[k].x, cc0);  cc1 = fmaf(fc, Dv[k].y, cc1);
        d0  = fmaf(fd, Dv[k].x, d0);   d1  = fmaf(fd, Dv[k].y, d1);
    }
    float2* op = (float2*)out + (size_t)r * 32 + lane;
    op[0]  = make_float2(a0, a1);
    op[32] = make_float2(b0, b1);
    op[64] = make_float2(cc0, cc1);
    op[96] = make_float2(d0, d1);
}

extern "C" void kernel_launch(void* const* d_in, const int* in_sizes, int n_in,
                              void* d_out, int out_size) {
    const float* x      = (const float*)d_in[0];
    const float* logits = (const float*)d_in[1];
    const float* embed  = (const float*)d_in[2];
    const float* W      = (const float*)d_in[3];
    const float* bias   = (const float*)d_in[4];
    float* out          = (float*)d_out;

    k1_stats<<<K1_MBLK + 1, TPB>>>((const float4*)x, logits, embed, W);
    k2_finalize<<<1, 1024>>>(bias);
    k3_main<<<K3_BLOCKS, TPB>>>(x, out);
}